// round 1
// baseline (speedup 1.0000x reference)
#include <cuda_runtime.h>
#include <cuda_bf16.h>
#include <cstdint>

#define S_LEN 4096
#define E_DIM 256
#define HH 256
#define G4 1024      // 4*HH
#define T_TAGS 9
#define START_TAG 7
#define STOP_TAG 8
#define NEG_VAL -10000.0f

// ---------------- device scratch (no allocations allowed) ----------------
__device__ float g_xg[2][S_LEN][G4];     // 32 MB: precomputed x@w_ih.T + b_ih + b_hh
__device__ float g_lstm[S_LEN][2 * HH];  // 8 MB: concat(hf, hb)
__device__ float g_frames[S_LEN][T_TAGS];

// =========================================================================
// Kernel 1: x_gates GEMM with embedding gather.
// C[R=2048][P=4096], R<1024 = forward rows (w_ih_f), else backward (w_ih_b).
// 64x64 tiles, K=256 in 4 chunks of 64, 256 threads, 4x4 micro-tile.
// =========================================================================
__global__ void xgates_kernel(const int* __restrict__ sentence,
                              const float* __restrict__ embed,
                              const float* __restrict__ w_ih_f,
                              const float* __restrict__ b_ih_f,
                              const float* __restrict__ b_hh_f,
                              const float* __restrict__ w_ih_b,
                              const float* __restrict__ b_ih_b,
                              const float* __restrict__ b_hh_b)
{
    __shared__ float s_x[64][65];
    __shared__ float s_w[64][65];
    __shared__ int   s_sent[64];

    int t  = threadIdx.x;            // 256 threads
    int tx = t & 15, ty = t >> 4;
    int bx = blockIdx.x;             // position tile (64 positions)
    int by = blockIdx.y;             // row tile (64 gate rows)

    if (t < 64) s_sent[t] = sentence[bx * 64 + t];
    __syncthreads();

    float acc[4][4] = {};

    for (int kc = 0; kc < 4; kc++) {
        int k0 = kc * 64;
        #pragma unroll
        for (int qq = 0; qq < 16; qq++) {
            int idx = t + 256 * qq;
            int i = idx >> 6, kk = idx & 63;
            s_x[i][kk] = embed[(long)s_sent[i] * E_DIM + k0 + kk];
        }
        #pragma unroll
        for (int qq = 0; qq < 16; qq++) {
            int idx = t + 256 * qq;
            int i = idx >> 6, kk = idx & 63;
            int R = by * 64 + i;
            const float* w = (R < 1024) ? w_ih_f : w_ih_b;
            int r = R & 1023;
            s_w[i][kk] = w[r * E_DIM + k0 + kk];
        }
        __syncthreads();
        #pragma unroll
        for (int kk = 0; kk < 64; kk++) {
            float a[4], b[4];
            #pragma unroll
            for (int i = 0; i < 4; i++) a[i] = s_w[ty * 4 + i][kk];
            #pragma unroll
            for (int j = 0; j < 4; j++) b[j] = s_x[tx * 4 + j][kk];
            #pragma unroll
            for (int i = 0; i < 4; i++)
                #pragma unroll
                for (int j = 0; j < 4; j++)
                    acc[i][j] += a[i] * b[j];
        }
        __syncthreads();
    }

    #pragma unroll
    for (int i = 0; i < 4; i++) {
        int R = by * 64 + ty * 4 + i;
        int dir = R >> 10;
        int r = R & 1023;
        float bias = dir ? (b_ih_b[r] + b_hh_b[r]) : (b_ih_f[r] + b_hh_f[r]);
        #pragma unroll
        for (int j = 0; j < 4; j++) {
            int p = bx * 64 + tx * 4 + j;
            g_xg[dir][p][r] = acc[i][j] + bias;
        }
    }
}

// =========================================================================
// Kernel 2: the serial recurrence. One 8-CTA cluster per direction.
// CTA rank k owns hidden units [k*32, k*32+32): gate rows q*256 + k*32 + u.
// 512 threads: warp w -> col chunk (w&3)*64, rows ((w>>2)*32 + lane).
// Weights (64 floats/thread) live in registers. h double-buffered in smem,
// broadcast cluster-wide via st.shared::cluster each step.
// =========================================================================
__device__ __forceinline__ uint32_t smem_u32(const void* p) {
    return (uint32_t)__cvta_generic_to_shared(p);
}

__global__ void __cluster_dims__(8, 1, 1) __launch_bounds__(512, 1)
lstm_kernel(const float* __restrict__ w_hh_f,
            const float* __restrict__ w_hh_b,
            const float* __restrict__ h0,
            const float* __restrict__ c0)
{
    __shared__ __align__(16) float sh_h[2][HH];
    __shared__ float sh_part[4][128];
    __shared__ float sh_act[128];

    int t = threadIdx.x;
    int w = t >> 5, l = t & 31;
    int chunk = w & 3;                         // 0..3 -> cols [chunk*64, +64)
    int row_local = ((w >> 2) << 5) + l;       // 0..127
    int dir = blockIdx.x >> 3;
    uint32_t rank;
    asm("mov.u32 %0, %%cluster_ctarank;" : "=r"(rank));
    int q = row_local >> 5;                    // gate: 0=i,1=f,2=g,3=o
    int unit = row_local & 31;
    int row_global = q * HH + (int)rank * 32 + unit;

    const float* whh = dir ? w_hh_b : w_hh_f;
    float4 wreg[16];
    {
        const float4* wp = (const float4*)(whh + row_global * HH + chunk * 64);
        #pragma unroll
        for (int i = 0; i < 16; i++) wreg[i] = wp[i];
    }

    if (t < HH) sh_h[0][t] = h0[dir * HH + t];
    float c = 0.f;
    if (w == 0) c = c0[dir * HH + (int)rank * 32 + l];

    const float* xg = &g_xg[dir][0][0];
    int s  = dir ? (S_LEN - 1) : 0;
    int ds = dir ? -1 : 1;

    float xg_pref = 0.f;
    if (chunk == 0) xg_pref = xg[s * G4 + row_global];

    __syncthreads();
    asm volatile("barrier.cluster.arrive.aligned;" ::: "memory");
    asm volatile("barrier.cluster.wait.aligned;" ::: "memory");

    int buf = 0;
    int outcol = dir * HH + (int)rank * 32 + l;

    for (int step = 0; step < S_LEN; step++) {
        // ---- stage 1: partial dot over this thread's 64 columns ----
        const float4* hp = (const float4*)(&sh_h[buf][chunk * 64]);
        float p0 = 0.f, p1 = 0.f, p2 = 0.f, p3 = 0.f;
        #pragma unroll
        for (int i = 0; i < 16; i += 4) {
            float4 h0v = hp[i + 0], h1v = hp[i + 1], h2v = hp[i + 2], h3v = hp[i + 3];
            p0 += wreg[i + 0].x * h0v.x + wreg[i + 0].y * h0v.y + wreg[i + 0].z * h0v.z + wreg[i + 0].w * h0v.w;
            p1 += wreg[i + 1].x * h1v.x + wreg[i + 1].y * h1v.y + wreg[i + 1].z * h1v.z + wreg[i + 1].w * h1v.w;
            p2 += wreg[i + 2].x * h2v.x + wreg[i + 2].y * h2v.y + wreg[i + 2].z * h2v.z + wreg[i + 2].w * h2v.w;
            p3 += wreg[i + 3].x * h3v.x + wreg[i + 3].y * h3v.y + wreg[i + 3].z * h3v.z + wreg[i + 3].w * h3v.w;
        }
        sh_part[chunk][row_local] = (p0 + p1) + (p2 + p3);
        __syncthreads();

        // ---- stage 2: gate sums + activations (128 threads, chunk 0) ----
        if (chunk == 0) {
            float gsum = xg_pref + sh_part[0][row_local] + sh_part[1][row_local]
                                 + sh_part[2][row_local] + sh_part[3][row_local];
            int sn = s + ds;
            if (sn >= 0 && sn < S_LEN) xg_pref = xg[sn * G4 + row_global];
            float a = (q == 2) ? tanhf(gsum) : (1.f / (1.f + expf(-gsum)));
            sh_act[row_local] = a;
        }
        __syncthreads();

        // ---- stage 3: cell update + cluster-wide h broadcast (warp 0) ----
        if (w == 0) {
            float iv = sh_act[l], fv = sh_act[32 + l], gv = sh_act[64 + l], ov = sh_act[96 + l];
            c = fv * c + iv * gv;
            float hn = ov * tanhf(c);
            g_lstm[s][outcol] = hn;
            uint32_t la = smem_u32(&sh_h[buf ^ 1][(int)rank * 32 + l]);
            #pragma unroll
            for (int peer = 0; peer < 8; peer++) {
                uint32_t ra;
                asm volatile("mapa.shared::cluster.u32 %0, %1, %2;" : "=r"(ra) : "r"(la), "r"(peer));
                asm volatile("st.shared::cluster.f32 [%0], %1;" :: "r"(ra), "f"(hn) : "memory");
            }
        }
        // release/acquire: orders the DSMEM stores before next step's reads
        asm volatile("barrier.cluster.arrive.aligned;" ::: "memory");
        asm volatile("barrier.cluster.wait.aligned;" ::: "memory");
        buf ^= 1;
        s += ds;
    }
}

// =========================================================================
// Kernel 3: emission scores frames[s][tag] = lstm_out[s] . W_out[tag] + b_out
// =========================================================================
__global__ void frames_kernel(const float* __restrict__ W_out,
                              const float* __restrict__ b_out)
{
    __shared__ float row[512];
    int s = blockIdx.x;
    int t = threadIdx.x;
    row[t] = g_lstm[s][t];
    __syncthreads();
    int wq = t >> 5, l = t & 31;
    if (wq < T_TAGS) {
        float p = 0.f;
        #pragma unroll
        for (int i = 0; i < 16; i++)
            p += row[l + 32 * i] * W_out[wq * 512 + l + 32 * i];
        #pragma unroll
        for (int o = 16; o > 0; o >>= 1)
            p += __shfl_down_sync(0xffffffffu, p, o);
        if (l == 0) g_frames[s][wq] = p + b_out[wq];
    }
}

// =========================================================================
// Kernel 4: Viterbi-style scan (logsumexp alpha + argmax backpointers),
// final score + backtrack. Frames and backpointers staged in smem so the
// serial chain never waits on L2.
// =========================================================================
__global__ void viterbi_kernel(const float* __restrict__ transitions,
                               float* __restrict__ out)
{
    extern __shared__ char dyn[];
    float* fr = (float*)dyn;                                    // S*9 floats
    unsigned char* bp = (unsigned char*)(fr + S_LEN * T_TAGS);  // S*9 bytes
    float* trs = (float*)(bp + S_LEN * T_TAGS);                 // 81
    float* alp = trs + 81;                                      // 16
    float* fin = alp + 16;                                      // 16

    int t = threadIdx.x;
    for (int idx = t; idx < S_LEN * T_TAGS; idx += blockDim.x)
        fr[idx] = ((const float*)g_frames)[idx];
    if (t < 81) trs[t] = transitions[t];
    if (t < T_TAGS) alp[t] = (t == START_TAG) ? 0.f : NEG_VAL;
    __syncthreads();

    if (t < 32) {
        int j = (t < T_TAGS) ? t : 0;
        bool act = (t < T_TAGS);
        float trj[9];
        #pragma unroll
        for (int i = 0; i < 9; i++) trj[i] = trs[i * 9 + j];

        for (int s = 0; s < S_LEN; s++) {
            float v[9];
            float best = -3.4e38f; int b = 0;
            #pragma unroll
            for (int i = 0; i < 9; i++) {
                float x = alp[i] + trj[i];
                v[i] = x;
                if (x > best) { best = x; b = i; }
            }
            float sum = 0.f;
            #pragma unroll
            for (int i = 0; i < 9; i++) sum += __expf(v[i] - best);
            float na = best + __logf(sum) + fr[s * 9 + j];
            if (act) bp[s * 9 + j] = (unsigned char)b;
            __syncwarp();
            if (act) alp[j] = na;
            __syncwarp();
        }
        if (act) fin[j] = alp[j] + trs[j * 9 + STOP_TAG];
        __syncwarp();
        if (t == 0) {
            float m = -3.4e38f; int bestj = 0;
            for (int k = 0; k < 9; k++) if (fin[k] > m) { m = fin[k]; bestj = k; }
            float sum = 0.f;
            for (int k = 0; k < 9; k++) sum += __expf(fin[k] - m);
            out[0] = m + __logf(sum);                 // score
            int tag = bestj;
            out[1 + (S_LEN - 1)] = (float)tag;        // tag at position S-1
            for (int s = S_LEN - 1; s >= 1; s--) {
                tag = bp[s * 9 + tag];
                out[s] = (float)tag;                  // out[1 + (s-1)]
            }
        }
    }
}

// =========================================================================
extern "C" void kernel_launch(void* const* d_in, const int* in_sizes, int n_in,
                              void* d_out, int out_size)
{
    const int*   sentence    = (const int*)d_in[0];
    const float* embed       = (const float*)d_in[1];
    const float* w_ih_f      = (const float*)d_in[2];
    const float* w_hh_f      = (const float*)d_in[3];
    const float* b_ih_f      = (const float*)d_in[4];
    const float* b_hh_f      = (const float*)d_in[5];
    const float* w_ih_b      = (const float*)d_in[6];
    const float* w_hh_b      = (const float*)d_in[7];
    const float* b_ih_b      = (const float*)d_in[8];
    const float* b_hh_b      = (const float*)d_in[9];
    const float* h0          = (const float*)d_in[10];
    const float* c0          = (const float*)d_in[11];
    const float* W_out       = (const float*)d_in[12];
    const float* b_out       = (const float*)d_in[13];
    const float* transitions = (const float*)d_in[14];
    float* out = (float*)d_out;

    dim3 g1(64, 32);
    xgates_kernel<<<g1, 256>>>(sentence, embed, w_ih_f, b_ih_f, b_hh_f,
                               w_ih_b, b_ih_b, b_hh_b);

    lstm_kernel<<<16, 512>>>(w_hh_f, w_hh_b, h0, c0);

    frames_kernel<<<S_LEN, 512>>>(W_out, b_out);

    size_t smem4 = (size_t)S_LEN * T_TAGS * sizeof(float)
                 + (size_t)S_LEN * T_TAGS
                 + 128 * sizeof(float);
    cudaFuncSetAttribute(viterbi_kernel,
                         cudaFuncAttributeMaxDynamicSharedMemorySize, (int)smem4);
    viterbi_kernel<<<1, 256, smem4>>>(transitions, out);
}